// round 5
// baseline (speedup 1.0000x reference)
#include <cuda_runtime.h>
#include <cuda_bf16.h>
#include <cstdint>

#define BATCH 16
#define NROW  196
#define CDIM  768
#define HDIM  512
#define ODIM  128
#define MTOT  (BATCH * NROW)   // 3136

#define TM 128
#define TN 128
#define TKC 64                  // K elements per chunk (64 bf16 = 128B = SW128 atom)
#define NTH 256
#define MT ((MTOT + TM - 1) / TM)   // 25
#define NT (HDIM / TN)              // 4
#define NCHUNK (CDIM / TKC)         // 12

#define TILE_BYTES (TM * 128)       // 16 KB per operand tile
// 1 KB align slack + 4 tiles + sacc (2*128 floats)
#define SMEM_DYN (1024 + 4 * TILE_BYTES + 2 * 128 * 4)

#define SW128(o) ((uint32_t)(o) ^ ((((uint32_t)(o)) >> 3) & 0x70u))

__device__ float g_s[2][BATCH][HDIM];

__device__ __forceinline__ uint32_t smem_u32(const void* p) {
    uint32_t a;
    asm("{ .reg .u64 t; cvta.to.shared.u64 t, %1; cvt.u32.u64 %0, t; }" : "=r"(a) : "l"(p));
    return a;
}

__device__ __forceinline__ void ldsm_x4(uint32_t& r0, uint32_t& r1, uint32_t& r2, uint32_t& r3,
                                        uint32_t addr) {
    asm volatile("ldmatrix.sync.aligned.m8n8.x4.shared.b16 {%0,%1,%2,%3}, [%4];"
                 : "=r"(r0), "=r"(r1), "=r"(r2), "=r"(r3) : "r"(addr));
}

__device__ __forceinline__ void mma_bf16(float* d, const uint32_t* a, const uint32_t* b) {
    asm volatile(
        "mma.sync.aligned.m16n8k16.row.col.f32.bf16.bf16.f32 "
        "{%0,%1,%2,%3}, {%4,%5,%6,%7}, {%8,%9}, {%0,%1,%2,%3};"
        : "+f"(d[0]), "+f"(d[1]), "+f"(d[2]), "+f"(d[3])
        : "r"(a[0]), "r"(a[1]), "r"(a[2]), "r"(a[3]), "r"(b[0]), "r"(b[1]));
}

__device__ __forceinline__ void split_pair(float a, float b, uint32_t& hi, uint32_t& lo) {
    __nv_bfloat16 ah = __float2bfloat16(a), bh = __float2bfloat16(b);
    __nv_bfloat16 al = __float2bfloat16(a - __bfloat162float(ah));
    __nv_bfloat16 bl = __float2bfloat16(b - __bfloat162float(bh));
    hi = (uint32_t)__bfloat16_as_ushort(ah) | ((uint32_t)__bfloat16_as_ushort(bh) << 16);
    lo = (uint32_t)__bfloat16_as_ushort(al) | ((uint32_t)__bfloat16_as_ushort(bl) << 16);
}

// ---------------- kernels ----------------

__global__ void zero_s_kernel() {
    int i = blockIdx.x * 256 + threadIdx.x;
    float* p = &g_s[0][0][0];
    if (i < 2 * BATCH * HDIM) p[i] = 0.0f;
}

__global__ __launch_bounds__(NTH, 1)
void lrbp_gemm_mma(const float* __restrict__ x1, const float* __restrict__ x2,
                   const float* __restrict__ W1, const float* __restrict__ W2) {
    extern __shared__ char smem[];
    const uint32_t sb = smem_u32(smem);
    const uint32_t ab = (sb + 1023) & ~1023u;   // 1024-aligned tile base
    char* tiles = smem + (ab - sb);

    char* sAhi = tiles;
    char* sAlo = tiles + TILE_BYTES;
    char* sBhi = tiles + 2 * TILE_BYTES;
    char* sBlo = tiles + 3 * TILE_BYTES;
    float* sacc = (float*)(tiles + 4 * TILE_BYTES);   // [2][128]
    const uint32_t uAhi = ab, uAlo = ab + TILE_BYTES,
                   uBhi = ab + 2 * TILE_BYTES, uBlo = ab + 3 * TILE_BYTES;

    const int which = blockIdx.z;
    const float* __restrict__ X = which ? x2 : x1;
    const float* __restrict__ W = which ? W2 : W1;
    const int m0 = blockIdx.x * TM;
    const int n0 = blockIdx.y * TN;
    const int tid = threadIdx.x;
    const int wid = tid >> 5;
    const int l = tid & 31;
    const int warp_m = wid >> 2;     // 0..1 -> 64 rows each
    const int warp_n = wid & 3;      // 0..3 -> 32 cols each

    if (tid < 256) {
        sacc[tid & 255] = 0.0f;      // zero sacc[2][128]
    }

    float acc[4][4][4];
#pragma unroll
    for (int mi = 0; mi < 4; mi++)
#pragma unroll
        for (int ni = 0; ni < 4; ni++)
#pragma unroll
            for (int j = 0; j < 4; j++) acc[mi][ni][j] = 0.0f;

    // ---- prefetch chunk 0 ----
    float4 av[8], bv[8];
    {
#pragma unroll
        for (int q = 0; q < 8; q++) {
            int f = tid + q * NTH;
            int row = f >> 4, kq = f & 15;
            int gr = m0 + row;
            av[q] = (gr < MTOT) ? *(const float4*)(X + (size_t)gr * CDIM + kq * 4)
                                : make_float4(0.f, 0.f, 0.f, 0.f);
        }
#pragma unroll
        for (int q = 0; q < 8; q++) {
            int f = tid + q * NTH;
            int k = f >> 5;
            int n4 = (f & 31) << 2;
            bv[q] = *(const float4*)(W + (size_t)k * HDIM + n0 + n4);
        }
    }

    for (int kc = 0; kc < NCHUNK; kc++) {
        __syncthreads();   // previous chunk's ldmatrix done reading smem

        // ---- convert + store to swizzled smem ----
#pragma unroll
        for (int q = 0; q < 8; q++) {
            int f = tid + q * NTH;
            int row = f >> 4, kq = f & 15;
            uint32_t h01, l01, h23, l23;
            split_pair(av[q].x, av[q].y, h01, l01);
            split_pair(av[q].z, av[q].w, h23, l23);
            uint32_t off = SW128(row * 128 + kq * 8);
            *(uint2*)(sAhi + off) = make_uint2(h01, h23);
            *(uint2*)(sAlo + off) = make_uint2(l01, l23);
        }
#pragma unroll
        for (int q = 0; q < 8; q++) {
            int f = tid + q * NTH;
            int k = f >> 5;
            int n4 = (f & 31) << 2;
            float vals[4] = {bv[q].x, bv[q].y, bv[q].z, bv[q].w};
#pragma unroll
            for (int i = 0; i < 4; i++) {
                __nv_bfloat16 h = __float2bfloat16(vals[i]);
                __nv_bfloat16 lo = __float2bfloat16(vals[i] - __bfloat162float(h));
                uint32_t off = SW128((n4 + i) * 128 + k * 2);
                *(uint16_t*)(sBhi + off) = __bfloat16_as_ushort(h);
                *(uint16_t*)(sBlo + off) = __bfloat16_as_ushort(lo);
            }
        }

        // ---- prefetch next chunk (LDG latency hides under MMA phase) ----
        if (kc + 1 < NCHUNK) {
            const int k0n = (kc + 1) * TKC;
#pragma unroll
            for (int q = 0; q < 8; q++) {
                int f = tid + q * NTH;
                int row = f >> 4, kq = f & 15;
                int gr = m0 + row;
                av[q] = (gr < MTOT) ? *(const float4*)(X + (size_t)gr * CDIM + k0n + kq * 4)
                                    : make_float4(0.f, 0.f, 0.f, 0.f);
            }
#pragma unroll
            for (int q = 0; q < 8; q++) {
                int f = tid + q * NTH;
                int k = f >> 5;
                int n4 = (f & 31) << 2;
                bv[q] = *(const float4*)(W + (size_t)(k0n + k) * HDIM + n0 + n4);
            }
        }

        __syncthreads();   // tile visible

        // ---- MMA phase ----
#pragma unroll
        for (int ks = 0; ks < 4; ks++) {
            const int kbase = ks * 16;
            uint32_t ahi[4][4], alo[4][4], bhi[4][2], blo[4][2];

            // A fragments (4 m16 tiles, hi + lo)
#pragma unroll
            for (int mi = 0; mi < 4; mi++) {
                int m8 = l >> 3;
                int r = warp_m * 64 + mi * 16 + ((m8 & 1) << 3) + (l & 7);
                int kcol = kbase + ((m8 >> 1) << 3);
                uint32_t off = SW128(r * 128 + kcol * 2);
                ldsm_x4(ahi[mi][0], ahi[mi][1], ahi[mi][2], ahi[mi][3], uAhi + off);
                ldsm_x4(alo[mi][0], alo[mi][1], alo[mi][2], alo[mi][3], uAlo + off);
            }
            // B fragments (2 n16 groups -> 4 n8 tiles, hi + lo)
#pragma unroll
            for (int g = 0; g < 2; g++) {
                int m8 = l >> 3;
                int n = warp_n * 32 + g * 16 + ((m8 >> 1) << 3) + (l & 7);
                int kcol = kbase + ((m8 & 1) << 3);
                uint32_t off = SW128(n * 128 + kcol * 2);
                uint32_t r0, r1, r2, r3;
                ldsm_x4(r0, r1, r2, r3, uBhi + off);
                bhi[2 * g][0] = r0; bhi[2 * g][1] = r1;
                bhi[2 * g + 1][0] = r2; bhi[2 * g + 1][1] = r3;
                ldsm_x4(r0, r1, r2, r3, uBlo + off);
                blo[2 * g][0] = r0; blo[2 * g][1] = r1;
                blo[2 * g + 1][0] = r2; blo[2 * g + 1][1] = r3;
            }

#pragma unroll
            for (int mi = 0; mi < 4; mi++)
#pragma unroll
                for (int ni = 0; ni < 4; ni++) {
                    mma_bf16(acc[mi][ni], ahi[mi], bhi[ni]);
                    mma_bf16(acc[mi][ni], ahi[mi], blo[ni]);
                    mma_bf16(acc[mi][ni], alo[mi], bhi[ni]);
                }
        }
    }

    // ---- epilogue: relu + batch-segmented column sums ----
    __syncthreads();   // sacc zero + last ldmatrix done

    const int b0 = m0 / NROW;
    const int bend = (b0 + 1) * NROW;

#pragma unroll
    for (int mi = 0; mi < 4; mi++) {
        int rb = m0 + warp_m * 64 + mi * 16 + (l >> 2);
#pragma unroll
        for (int ni = 0; ni < 4; ni++) {
            int cb = warp_n * 32 + ni * 8 + (l & 3) * 2;
#pragma unroll
            for (int j = 0; j < 4; j++) {
                int gr = rb + ((j >> 1) << 3);    // +8 for j=2,3
                int c = cb + (j & 1);
                if (gr < MTOT) {
                    int slot = (gr < bend) ? 0 : 1;
                    float v = fmaxf(acc[mi][ni][j], 0.0f);
                    atomicAdd(&sacc[slot * 128 + c], v);
                }
            }
        }
    }
    __syncthreads();

    if (tid < 128) {
        atomicAdd(&g_s[which][b0][n0 + tid], sacc[tid]);
    } else if (b0 + 1 < BATCH) {
        int c = tid - 128;
        atomicAdd(&g_s[which][b0 + 1][n0 + c], sacc[128 + c]);
    }
}

// out[b,o] = sum_h s1[b,h]*s2[b,h]*Wp[h,o] + bp[o]*N1*N2
__global__ __launch_bounds__(ODIM)
void final_kernel(const float* __restrict__ Wp, const float* __restrict__ bp,
                  float* __restrict__ out) {
    const int b = blockIdx.x;
    const int o = threadIdx.x;

    __shared__ float sprod[HDIM];
    for (int h = o; h < HDIM; h += ODIM)
        sprod[h] = g_s[0][b][h] * g_s[1][b][h];
    __syncthreads();

    float acc = 0.0f;
#pragma unroll 8
    for (int h = 0; h < HDIM; h++)
        acc = fmaf(sprod[h], Wp[(size_t)h * ODIM + o], acc);

    out[b * ODIM + o] = acc + bp[o] * (float)(NROW * NROW);
}

extern "C" void kernel_launch(void* const* d_in, const int* in_sizes, int n_in,
                              void* d_out, int out_size) {
    const float* x1 = (const float*)d_in[0];
    const float* x2 = (const float*)d_in[1];
    const float* W1 = (const float*)d_in[2];
    const float* W2 = (const float*)d_in[3];
    const float* Wp = (const float*)d_in[4];
    const float* bp = (const float*)d_in[5];
    float* out = (float*)d_out;

    cudaFuncSetAttribute(lrbp_gemm_mma, cudaFuncAttributeMaxDynamicSharedMemorySize, SMEM_DYN);

    zero_s_kernel<<<(2 * BATCH * HDIM + 255) / 256, 256>>>();
    lrbp_gemm_mma<<<dim3(MT, NT, 2), NTH, SMEM_DYN>>>(x1, x2, W1, W2);
    final_kernel<<<BATCH, ODIM>>>(Wp, bp, out);
}

// round 6
// speedup vs baseline: 2.0114x; 2.0114x over previous
#include <cuda_runtime.h>
#include <cstdint>

#define BATCH 16
#define NROW  196
#define CDIM  768
#define HDIM  512
#define ODIM  128
#define MTOT  (BATCH * NROW)   // 3136

#define TM 128
#define TN 64
#define TK 16
#define NTHREADS 128
#define MTILES ((MTOT + TM - 1) / TM)   // 25
#define NTILES (HDIM / TN)              // 8

// Scratch: s[which][b][h] = sum_i relu( x_which[b,i,:] . W_which[:,h] )
__device__ float g_s[2][BATCH][HDIM];

// ---------------- f32x2 helpers ----------------

__device__ __forceinline__ void ffma2(unsigned long long& d, unsigned long long a,
                                      unsigned long long b) {
    asm("fma.rn.f32x2 %0, %1, %2, %0;" : "+l"(d) : "l"(a), "l"(b));
}

__device__ __forceinline__ unsigned long long dup2(float w) {
    unsigned long long r;
    uint32_t u = __float_as_uint(w);
    asm("mov.b64 %0, {%1, %1};" : "=l"(r) : "r"(u));
    return r;
}

__device__ __forceinline__ void unpack2(unsigned long long v, float& lo, float& hi) {
    uint32_t l_, h_;
    asm("mov.b64 {%0, %1}, %2;" : "=r"(l_), "=r"(h_) : "l"(v));
    lo = __uint_as_float(l_);
    hi = __uint_as_float(h_);
}

// ---------------- kernels ----------------

__global__ void zero_s_kernel() {
    int i = blockIdx.x * 256 + threadIdx.x;
    float* p = &g_s[0][0][0];
    if (i < 2 * BATCH * HDIM) p[i] = 0.0f;
}

// GEMM [3136,768] x [768,512] with ReLU + per-batch row-sum epilogue.
// f32x2 packed math: accumulators pair adjacent m rows.
__global__ __launch_bounds__(NTHREADS, 3)
void gemm_relu_rowsum_f32x2(const float* __restrict__ x1,
                            const float* __restrict__ x2,
                            const float* __restrict__ W1,
                            const float* __restrict__ W2) {
    const int which = blockIdx.z;
    const float* __restrict__ X = which ? x2 : x1;
    const float* __restrict__ W = which ? W2 : W1;

    const int m0 = blockIdx.x * TM;
    const int n0 = blockIdx.y * TN;
    const int tid = threadIdx.x;
    const int tr = tid >> 3;   // 0..15 : row group (8 rows each)
    const int tc = tid & 7;    // 0..7  : col group (8 cols each)

    __shared__ float Xs[TK][TM];                  // 8 KB, Xs[k][row]
    __shared__ unsigned long long Wd[TK][TN];     // 8 KB, dup-pair permuted layout
    // Wd slot for logical col n (0..63): p = (n&7)>>1, slot = p*16 + (n>>3)*2 + (n&1)

    unsigned long long acc[4][8];   // [m-pair][n]
#pragma unroll
    for (int i = 0; i < 4; i++)
#pragma unroll
        for (int j = 0; j < 8; j++) acc[i][j] = 0ull;

    const int xrow = m0 + tid;            // each thread owns one X row per tile
    const bool xvalid = (xrow < MTOT);
    const float* xbase = X + (size_t)xrow * CDIM;

    const int widx0 = tid * 2;   // W: 1024 floats = 256 float4; thread loads 2

    for (int k0 = 0; k0 < CDIM; k0 += TK) {
        // ---- global loads into registers ----
        float4 xv[4];
        if (xvalid) {
            const float4* src = (const float4*)(xbase + k0);
#pragma unroll
            for (int q = 0; q < 4; q++) xv[q] = src[q];
        } else {
#pragma unroll
            for (int q = 0; q < 4; q++) xv[q] = make_float4(0.f, 0.f, 0.f, 0.f);
        }
        float4 wv[2];
#pragma unroll
        for (int i = 0; i < 2; i++) {
            int idx = widx0 + i;
            int r = idx >> 4;          // k row within tile (0..15)
            int c4 = idx & 15;         // float4 index within 64 cols
            wv[i] = *(const float4*)(W + (size_t)(k0 + r) * HDIM + n0 + c4 * 4);
        }

        __syncthreads();   // previous tile's compute done

        // ---- store to smem ----
#pragma unroll
        for (int q = 0; q < 4; q++) {
            Xs[q * 4 + 0][tid] = xv[q].x;
            Xs[q * 4 + 1][tid] = xv[q].y;
            Xs[q * 4 + 2][tid] = xv[q].z;
            Xs[q * 4 + 3][tid] = xv[q].w;
        }
#pragma unroll
        for (int i = 0; i < 2; i++) {
            int idx = widx0 + i;
            int r = idx >> 4;
            int c4 = idx & 15;
            float vals[4] = {wv[i].x, wv[i].y, wv[i].z, wv[i].w};
#pragma unroll
            for (int q = 0; q < 4; q++) {
                int n = c4 * 4 + q;
                int slot = ((n & 7) >> 1) * 16 + (n >> 3) * 2 + (n & 1);
                Wd[r][slot] = dup2(vals[q]);
            }
        }

        __syncthreads();   // tile visible

        // ---- compute: per k, 4 LDS.128 + 32 FFMA2 ----
#pragma unroll
        for (int kk = 0; kk < TK; kk++) {
            unsigned long long a2[4], b2[8];
            {
                double2 t0 = *(const double2*)&Xs[kk][tr * 8];
                double2 t1 = *(const double2*)&Xs[kk][tr * 8 + 4];
                a2[0] = __double_as_longlong(t0.x);
                a2[1] = __double_as_longlong(t0.y);
                a2[2] = __double_as_longlong(t1.x);
                a2[3] = __double_as_longlong(t1.y);
            }
#pragma unroll
            for (int p = 0; p < 4; p++) {
                double2 t = *(const double2*)&Wd[kk][p * 16 + tc * 2];
                b2[2 * p]     = __double_as_longlong(t.x);
                b2[2 * p + 1] = __double_as_longlong(t.y);
            }
#pragma unroll
            for (int i = 0; i < 4; i++)
#pragma unroll
                for (int j = 0; j < 8; j++)
                    ffma2(acc[i][j], a2[i], b2[j]);
        }
    }

    // ---- unpack to scalar 8x8 ----
    float accf[8][8];
#pragma unroll
    for (int i = 0; i < 4; i++)
#pragma unroll
        for (int j = 0; j < 8; j++)
            unpack2(acc[i][j], accf[2 * i][j], accf[2 * i + 1][j]);

    // ---- epilogue: relu, group rows by batch, atomic into g_s ----
    const int rowbase = m0 + tr * 8;
    const int colbase = n0 + tc * 8;

    int i = 0;
    while (i < 8) {
        int gr = rowbase + i;
        if (gr >= MTOT) break;
        int b = gr / NROW;
        int bend = (b + 1) * NROW;   // exclusive global-row bound for this batch
        float cs[8];
#pragma unroll
        for (int j = 0; j < 8; j++) cs[j] = 0.0f;
        while (i < 8 && (rowbase + i) < bend && (rowbase + i) < MTOT) {
#pragma unroll
            for (int j = 0; j < 8; j++) cs[j] += fmaxf(accf[i][j], 0.0f);
            i++;
        }
        float* dst = &g_s[which][b][colbase];
#pragma unroll
        for (int j = 0; j < 8; j++) atomicAdd(dst + j, cs[j]);
    }
}

// out[b,o] = sum_h s1[b,h]*s2[b,h]*Wp[h,o] + bp[o]*N1*N2
__global__ __launch_bounds__(ODIM)
void final_kernel(const float* __restrict__ Wp,
                  const float* __restrict__ bp,
                  float* __restrict__ out) {
    const int b = blockIdx.x;
    const int o = threadIdx.x;

    __shared__ float sprod[HDIM];
    for (int h = o; h < HDIM; h += ODIM)
        sprod[h] = g_s[0][b][h] * g_s[1][b][h];
    __syncthreads();

    float acc = 0.0f;
#pragma unroll 8
    for (int h = 0; h < HDIM; h++)
        acc = fmaf(sprod[h], Wp[(size_t)h * ODIM + o], acc);

    out[b * ODIM + o] = acc + bp[o] * (float)(NROW * NROW);
}

extern "C" void kernel_launch(void* const* d_in, const int* in_sizes, int n_in,
                              void* d_out, int out_size) {
    const float* x1 = (const float*)d_in[0];
    const float* x2 = (const float*)d_in[1];
    const float* W1 = (const float*)d_in[2];
    const float* W2 = (const float*)d_in[3];
    const float* Wp = (const float*)d_in[4];
    const float* bp = (const float*)d_in[5];
    float* out = (float*)d_out;

    zero_s_kernel<<<(2 * BATCH * HDIM + 255) / 256, 256>>>();
    gemm_relu_rowsum_f32x2<<<dim3(MTILES, NTILES, 2), NTHREADS>>>(x1, x2, W1, W2);
    final_kernel<<<BATCH, ODIM>>>(Wp, bp, out);
}